// round 15
// baseline (speedup 1.0000x reference)
#include <cuda_runtime.h>
#include <cuda_fp16.h>
#include <cuda_bf16.h>
#include <cstdint>

#define NN 100000
#define EE 1600000
#define TE (EE + NN)
#define NB_SCAN ((NN + 1023) / 1024)
#define SX2_STRIDE 136

// ---------------- scratch (static device globals; no allocation) -----------
__device__ __align__(16) __half g_h1[NN * 128];    // layer1 linear output (fp16)
__device__ __align__(16) float  g_out1[NN * 128];  // relu(layer1 agg out)
__device__ __align__(16) __half g_h2[NN * 32];     // layer2 linear output (fp16)
__device__ __align__(16) float g_asrc1[NN * 4];
__device__ __align__(16) float g_adst1[NN * 4];
__device__ __align__(16) float g_asrc2[NN];
__device__ __align__(16) float g_adst2[NN];
__device__ __align__(16) float g_alpha1[(size_t)TE * 4];  // per-edge exp, 4 heads
__device__ __align__(16) float g_alpha2[TE];
__device__ __align__(16) float g_rden1[NN * 4];           // 1/denominator
__device__ __align__(16) float g_rden2[NN];
__device__ __align__(16) unsigned short g_w1hi[128 * 136];
__device__ __align__(16) unsigned short g_w1lo[128 * 136];
__device__ int   g_deg[NN];
__device__ int   g_rowstart[NN + 1];
__device__ int   g_cursor[NN];
__device__ int   g_csr[TE];
__device__ int   g_blockval[NB_SCAN];
__device__ int   g_blockflag[NB_SCAN];
__device__ int   g_is32;

__device__ __forceinline__ float lrelu(float x) { return x > 0.f ? x : 0.2f * x; }

__device__ __forceinline__ unsigned long long pack2(float a, float b) {
    unsigned long long r;
    asm("mov.b64 %0, {%1, %2};" : "=l"(r) : "f"(a), "f"(b));
    return r;
}
__device__ __forceinline__ void unpack2(unsigned long long p, float& a, float& b) {
    asm("mov.b64 {%0, %1}, %2;" : "=f"(a), "=f"(b) : "l"(p));
}
__device__ __forceinline__ void ffma2(unsigned long long& acc, unsigned long long a,
                                      unsigned long long b) {
    asm("fma.rn.f32x2 %0, %1, %2, %0;" : "+l"(acc) : "l"(a), "l"(b));
}

__device__ __forceinline__ uint32_t smem_u32(const void* p) {
    uint32_t a;
    asm("{ .reg .u64 t; cvta.to.shared.u64 t, %1; cvt.u32.u64 %0, t; }" : "=r"(a) : "l"(p));
    return a;
}

__device__ __forceinline__ void ldm4(uint32_t addr, uint32_t& r0, uint32_t& r1,
                                     uint32_t& r2, uint32_t& r3) {
    asm volatile("ldmatrix.sync.aligned.m8n8.x4.shared.b16 {%0,%1,%2,%3}, [%4];"
                 : "=r"(r0), "=r"(r1), "=r"(r2), "=r"(r3) : "r"(addr));
}

__device__ __forceinline__ void mma16816(float* c, uint32_t a0, uint32_t a1, uint32_t a2,
                                         uint32_t a3, uint32_t b0, uint32_t b1) {
    asm volatile(
        "mma.sync.aligned.m16n8k16.row.col.f32.bf16.bf16.f32 "
        "{%0,%1,%2,%3}, {%4,%5,%6,%7}, {%8,%9}, {%0,%1,%2,%3};"
        : "+f"(c[0]), "+f"(c[1]), "+f"(c[2]), "+f"(c[3])
        : "r"(a0), "r"(a1), "r"(a2), "r"(a3), "r"(b0), "r"(b1));
}

// ---------------- init + dtype detect + W1 bf16-split precompute -----------
__global__ void k_init(const void* __restrict__ ei, const float* __restrict__ W1) {
    int i = blockIdx.x * blockDim.x + threadIdx.x;
    if (i < NN) { g_deg[i] = 1; g_cursor[i] = 0; }
    if (i < NB_SCAN) g_blockflag[i] = 0;
    if (i < 16384) {
        int k = i >> 7, n = i & 127;
        float w = W1[i];
        __nv_bfloat16 hi = __float2bfloat16(w);
        __nv_bfloat16 lo = __float2bfloat16(w - __bfloat162float(hi));
        g_w1hi[n * 136 + k] = *(unsigned short*)&hi;
        g_w1lo[n * 136 + k] = *(unsigned short*)&lo;
    }
    if (i == 0) {
        const long long* p = (const long long*)ei;
        int bad = 0;
        for (int j = 0; j < 64; j++) {
            long long v = p[j];
            if (v < 0 || v >= NN) bad = 1;
        }
        g_is32 = bad;
    }
}

__device__ __forceinline__ int load_src(const void* ei, int e) {
    return g_is32 ? ((const int*)ei)[e] : (int)((const long long*)ei)[e];
}
__device__ __forceinline__ int load_dst(const void* ei, int e) {
    return g_is32 ? ((const int*)ei)[EE + e] : (int)((const long long*)ei)[EE + e];
}

// ---------------- CSR build -------------------------------------------------
__global__ void k_count(const void* __restrict__ ei) {
    int e = blockIdx.x * blockDim.x + threadIdx.x;
    if (e < EE) {
        int d = load_dst(ei, e);
        if ((unsigned)d < NN) atomicAdd(&g_deg[d], 1);
    }
}

__global__ void k_scan(void) {
    __shared__ int sh[1024];
    __shared__ int s_excl;
    int t = threadIdx.x;
    int b = blockIdx.x;
    int i = b * 1024 + t;
    int v = (i < NN) ? g_deg[i] : 0;
    sh[t] = v;
    __syncthreads();
    #pragma unroll
    for (int off = 1; off < 1024; off <<= 1) {
        int a = (t >= off) ? sh[t - off] : 0;
        __syncthreads();
        sh[t] += a;
        __syncthreads();
    }
    if (t == 1023) {
        g_blockval[b] = sh[1023];
        __threadfence();
        atomicExch(&g_blockflag[b], 1);
    }
    if (t < 32) {
        int excl = 0;
        for (int w0 = b - 1; w0 >= 0; w0 -= 32) {
            int idx = w0 - t;
            int val = 0;
            if (idx >= 0) {
                while (atomicAdd(&g_blockflag[idx], 0) == 0) {}
                __threadfence();
                val = g_blockval[idx];
            }
            #pragma unroll
            for (int off = 16; off; off >>= 1)
                val += __shfl_xor_sync(0xffffffffu, val, off);
            excl += val;
        }
        if (t == 0) s_excl = excl;
    }
    __syncthreads();
    if (i < NN) g_rowstart[i + 1] = sh[t] + s_excl;
    if (i == 0) g_rowstart[0] = 0;
}

__global__ void k_fill(const void* __restrict__ ei) {
    int t = blockIdx.x * blockDim.x + threadIdx.x;
    if (t >= TE) return;
    int s, d;
    if (t < EE) {
        s = load_src(ei, t);
        d = load_dst(ei, t);
    } else {
        s = d = t - EE;
    }
    if ((unsigned)s >= NN || (unsigned)d >= NN) return;
    int pos = g_rowstart[d] + atomicAdd(&g_cursor[d], 1);
    if ((unsigned)pos < TE) g_csr[pos] = s;
}

// ---------------- GEMM1 via mma.sync bf16 (split x3) + fused att1 ----------
#define XHI_OFF 1024
#define XLO_OFF 18432
#define WHI_OFF 35840
#define WLO_OFF 70656
#define G1_SMEM 105472

__global__ void __launch_bounds__(256, 2)
k_gemm1(const float* __restrict__ x,
        const float* __restrict__ att_src, const float* __restrict__ att_dst) {
    extern __shared__ char sm[];
    uint32_t smb = smem_u32(sm);
    int tid = threadIdx.x;
    int wid = tid >> 5, lane = tid & 31;
    int row0 = blockIdx.x * 64;

    float* s_as = (float*)(sm);
    float* s_ad = (float*)(sm + 512);
    if (tid < 128) {
        s_as[tid] = att_src[tid];
        s_ad[tid] = att_dst[tid];
    }

    {
        const uint4* WH4 = (const uint4*)g_w1hi;
        const uint4* WL4 = (const uint4*)g_w1lo;
        uint4* sWH = (uint4*)(sm + WHI_OFF);
        uint4* sWL = (uint4*)(sm + WLO_OFF);
        #pragma unroll
        for (int j = tid; j < 2176; j += 256) {
            sWH[j] = WH4[j];
            sWL[j] = WL4[j];
        }
    }

    {
        int r = tid >> 2;
        int ks = (tid & 3) * 32;
        int gr = row0 + r;
        const float4* X4 = (const float4*)x;
        char* xh = sm + XHI_OFF + r * 272 + ks * 2;
        char* xl = sm + XLO_OFF + r * 272 + ks * 2;
        #pragma unroll
        for (int j = 0; j < 8; j++) {
            float4 v = (gr < NN) ? X4[(size_t)gr * 32 + (ks >> 2) + j]
                                 : make_float4(0.f, 0.f, 0.f, 0.f);
            __nv_bfloat16 hx = __float2bfloat16(v.x);
            __nv_bfloat16 hy = __float2bfloat16(v.y);
            __nv_bfloat16 hz = __float2bfloat16(v.z);
            __nv_bfloat16 hw = __float2bfloat16(v.w);
            __nv_bfloat16 lx = __float2bfloat16(v.x - __bfloat162float(hx));
            __nv_bfloat16 ly = __float2bfloat16(v.y - __bfloat162float(hy));
            __nv_bfloat16 lz = __float2bfloat16(v.z - __bfloat162float(hz));
            __nv_bfloat16 lw = __float2bfloat16(v.w - __bfloat162float(hw));
            __nv_bfloat162 h01 = __halves2bfloat162(hx, hy);
            __nv_bfloat162 h23 = __halves2bfloat162(hz, hw);
            __nv_bfloat162 l01 = __halves2bfloat162(lx, ly);
            __nv_bfloat162 l23 = __halves2bfloat162(lz, lw);
            uint2 hv, lv;
            hv.x = *(uint32_t*)&h01; hv.y = *(uint32_t*)&h23;
            lv.x = *(uint32_t*)&l01; lv.y = *(uint32_t*)&l23;
            *(uint2*)(xh + j * 8) = hv;
            *(uint2*)(xl + j * 8) = lv;
        }
    }
    __syncthreads();

    int m0 = (wid >> 1) * 16;
    int ch = (wid & 1) * 64;
    int q = lane >> 3, rr = lane & 7;
    uint32_t aRow = (uint32_t)(m0 + rr + (q & 1) * 8);
    uint32_t aOffH = XHI_OFF + aRow * 272 + (uint32_t)(q >> 1) * 16;
    uint32_t aOffL = XLO_OFF + aRow * 272 + (uint32_t)(q >> 1) * 16;
    uint32_t bRow = (uint32_t)(ch + rr + (q >> 1) * 8);
    uint32_t bOffH = WHI_OFF + bRow * 272 + (uint32_t)(q & 1) * 16;
    uint32_t bOffL = WLO_OFF + bRow * 272 + (uint32_t)(q & 1) * 16;

    float c[8][4];
    #pragma unroll
    for (int nt = 0; nt < 8; nt++)
        #pragma unroll
        for (int e = 0; e < 4; e++) c[nt][e] = 0.f;

    #pragma unroll
    for (int kt = 0; kt < 8; kt++) {
        uint32_t ah0, ah1, ah2, ah3, al0, al1, al2, al3;
        ldm4(smb + aOffH + kt * 32, ah0, ah1, ah2, ah3);
        ldm4(smb + aOffL + kt * 32, al0, al1, al2, al3);
        #pragma unroll
        for (int np = 0; np < 4; np++) {
            uint32_t bh0, bh1, bh2, bh3, bl0, bl1, bl2, bl3;
            ldm4(smb + bOffH + np * 4352 + kt * 32, bh0, bh1, bh2, bh3);
            ldm4(smb + bOffL + np * 4352 + kt * 32, bl0, bl1, bl2, bl3);
            mma16816(c[np * 2],     ah0, ah1, ah2, ah3, bh0, bh1);
            mma16816(c[np * 2],     al0, al1, al2, al3, bh0, bh1);
            mma16816(c[np * 2],     ah0, ah1, ah2, ah3, bl0, bl1);
            mma16816(c[np * 2 + 1], ah0, ah1, ah2, ah3, bh2, bh3);
            mma16816(c[np * 2 + 1], al0, al1, al2, al3, bh2, bh3);
            mma16816(c[np * 2 + 1], ah0, ah1, ah2, ah3, bl2, bl3);
        }
    }

    int g = lane >> 2, qq = lane & 3;
    int gr0 = row0 + m0 + g;
    int gr1 = gr0 + 8;

    #pragma unroll
    for (int nt = 0; nt < 8; nt++) {
        int col = ch + nt * 8 + qq * 2;
        if (gr0 < NN)
            *(__half2*)&g_h1[(size_t)gr0 * 128 + col] = __floats2half2_rn(c[nt][0], c[nt][1]);
        if (gr1 < NN)
            *(__half2*)&g_h1[(size_t)gr1 * 128 + col] = __floats2half2_rn(c[nt][2], c[nt][3]);
    }

    #pragma unroll
    for (int hl = 0; hl < 2; hl++) {
        int gh = (ch >> 5) + hl;
        float s0 = 0.f, d0 = 0.f, s1 = 0.f, d1 = 0.f;
        #pragma unroll
        for (int t = 0; t < 4; t++) {
            int nt = hl * 4 + t;
            int col = ch + nt * 8 + qq * 2;
            float av0 = s_as[col], av1 = s_as[col + 1];
            float dv0 = s_ad[col], dv1 = s_ad[col + 1];
            s0 += c[nt][0] * av0 + c[nt][1] * av1;
            d0 += c[nt][0] * dv0 + c[nt][1] * dv1;
            s1 += c[nt][2] * av0 + c[nt][3] * av1;
            d1 += c[nt][2] * dv0 + c[nt][3] * dv1;
        }
        s0 += __shfl_xor_sync(0xffffffffu, s0, 1); s0 += __shfl_xor_sync(0xffffffffu, s0, 2);
        d0 += __shfl_xor_sync(0xffffffffu, d0, 1); d0 += __shfl_xor_sync(0xffffffffu, d0, 2);
        s1 += __shfl_xor_sync(0xffffffffu, s1, 1); s1 += __shfl_xor_sync(0xffffffffu, s1, 2);
        d1 += __shfl_xor_sync(0xffffffffu, d1, 1); d1 += __shfl_xor_sync(0xffffffffu, d1, 2);
        if (qq == 0) {
            if (gr0 < NN) { g_asrc1[gr0 * 4 + gh] = s0; g_adst1[gr0 * 4 + gh] = d0; }
            if (gr1 < NN) { g_asrc1[gr1 * 4 + gh] = s1; g_adst1[gr1 * 4 + gh] = d1; }
        }
    }
}

// ---------------- alpha pass L1: one edge per LANE -------------------------
// warp per node; lane i handles edge i, i+32, ... ; exp computed once per edge.
__global__ void k_alpha1(void) {
    int warp = threadIdx.x >> 5, lane = threadIdx.x & 31;
    int n = blockIdx.x * 16 + warp;
    if (n >= NN) return;
    int base = g_rowstart[n];
    int K = g_rowstart[n + 1] - base;
    float4 ad = ((const float4*)g_adst1)[n];

    float4 den = make_float4(0.f, 0.f, 0.f, 0.f);
    for (int i = lane; i < K; i += 32) {
        int s = g_csr[base + i];
        float4 as = ((const float4*)g_asrc1)[s];
        float4 e;
        e.x = __expf(lrelu(as.x + ad.x));
        e.y = __expf(lrelu(as.y + ad.y));
        e.z = __expf(lrelu(as.z + ad.z));
        e.w = __expf(lrelu(as.w + ad.w));
        ((float4*)g_alpha1)[base + i] = e;
        den.x += e.x; den.y += e.y; den.z += e.z; den.w += e.w;
    }
    #pragma unroll
    for (int off = 16; off; off >>= 1) {
        den.x += __shfl_xor_sync(0xffffffffu, den.x, off);
        den.y += __shfl_xor_sync(0xffffffffu, den.y, off);
        den.z += __shfl_xor_sync(0xffffffffu, den.z, off);
        den.w += __shfl_xor_sync(0xffffffffu, den.w, off);
    }
    if (lane == 0) {
        float4 r;
        r.x = 1.f / (den.x + 1e-16f);
        r.y = 1.f / (den.y + 1e-16f);
        r.z = 1.f / (den.z + 1e-16f);
        r.w = 1.f / (den.w + 1e-16f);
        ((float4*)g_rden1)[n] = r;
    }
}

// ---------------- aggregation L1: pure weighted gather ----------------------
__global__ void k_agg1(const float* __restrict__ b1) {
    int warp = threadIdx.x >> 5, lane = threadIdx.x & 31;
    int n = blockIdx.x * 16 + warp;
    if (n >= NN) return;
    int base = g_rowstart[n];
    int K = g_rowstart[n + 1] - base;
    int head = lane >> 3;

    const uint2* H2 = (const uint2*)g_h1;
    const float* AL = g_alpha1;
    const int* csr = g_csr + base;

    float4 acc = make_float4(0.f, 0.f, 0.f, 0.f);
    int i = 0;
    for (; i + 3 < K; i += 4) {
        int s0 = csr[i], s1 = csr[i + 1], s2 = csr[i + 2], s3 = csr[i + 3];
        float e0 = AL[(size_t)(base + i) * 4 + head];
        float e1 = AL[(size_t)(base + i + 1) * 4 + head];
        float e2 = AL[(size_t)(base + i + 2) * 4 + head];
        float e3 = AL[(size_t)(base + i + 3) * 4 + head];
        uint2 v0 = H2[(size_t)s0 * 32 + lane];
        uint2 v1 = H2[(size_t)s1 * 32 + lane];
        uint2 v2 = H2[(size_t)s2 * 32 + lane];
        uint2 v3 = H2[(size_t)s3 * 32 + lane];
        float2 f0a = __half22float2(*(__half2*)&v0.x);
        float2 f0b = __half22float2(*(__half2*)&v0.y);
        float2 f1a = __half22float2(*(__half2*)&v1.x);
        float2 f1b = __half22float2(*(__half2*)&v1.y);
        float2 f2a = __half22float2(*(__half2*)&v2.x);
        float2 f2b = __half22float2(*(__half2*)&v2.y);
        float2 f3a = __half22float2(*(__half2*)&v3.x);
        float2 f3b = __half22float2(*(__half2*)&v3.y);
        acc.x += (e0 * f0a.x + e1 * f1a.x) + (e2 * f2a.x + e3 * f3a.x);
        acc.y += (e0 * f0a.y + e1 * f1a.y) + (e2 * f2a.y + e3 * f3a.y);
        acc.z += (e0 * f0b.x + e1 * f1b.x) + (e2 * f2b.x + e3 * f3b.x);
        acc.w += (e0 * f0b.y + e1 * f1b.y) + (e2 * f2b.y + e3 * f3b.y);
    }
    for (; i < K; i++) {
        int s0 = csr[i];
        float e0 = AL[(size_t)(base + i) * 4 + head];
        uint2 v0 = H2[(size_t)s0 * 32 + lane];
        float2 f0a = __half22float2(*(__half2*)&v0.x);
        float2 f0b = __half22float2(*(__half2*)&v0.y);
        acc.x += e0 * f0a.x;
        acc.y += e0 * f0a.y;
        acc.z += e0 * f0b.x;
        acc.w += e0 * f0b.y;
    }

    float inv = g_rden1[n * 4 + head];
    float4 b = ((const float4*)b1)[lane];
    float4 o;
    o.x = fmaxf(acc.x * inv + b.x, 0.f);
    o.y = fmaxf(acc.y * inv + b.y, 0.f);
    o.z = fmaxf(acc.z * inv + b.z, 0.f);
    o.w = fmaxf(acc.w * inv + b.w, 0.f);
    ((float4*)g_out1)[(size_t)n * 32 + lane] = o;
}

// ---------------- GEMM2: h2 = out1 @ W2 (128x32) + fused attention coeffs --
__global__ void k_gemm2(const float* __restrict__ W2,
                        const float* __restrict__ att_src, const float* __restrict__ att_dst) {
    extern __shared__ float smf[];
    float* sW = smf;
    float* sX = smf + 128 * 32;
    int tid = threadIdx.x;
    int row0 = blockIdx.x * 128;

    float4* sW4 = (float4*)sW;
    const float4* W4 = (const float4*)W2;
    for (int j = tid; j < 1024; j += 256) sW4[j] = W4[j];

    const float4* X4 = (const float4*)g_out1;
    for (int j = tid; j < 4096; j += 256) {
        int r = j >> 5, c = j & 31;
        int gr = row0 + r;
        float4 v = (gr < NN) ? X4[(size_t)gr * 32 + c] : make_float4(0.f, 0.f, 0.f, 0.f);
        *(float4*)&sX[r * SX2_STRIDE + c * 4] = v;
    }
    __syncthreads();

    int tc = tid & 7;
    int tr = tid >> 3;
    unsigned long long accp[4][2];
    #pragma unroll
    for (int m = 0; m < 4; m++) { accp[m][0] = 0ull; accp[m][1] = 0ull; }

    for (int k4 = 0; k4 < 32; k4++) {
        float4 xq[4];
        #pragma unroll
        for (int m = 0; m < 4; m++)
            xq[m] = *(const float4*)&sX[(tr + 32 * m) * SX2_STRIDE + k4 * 4];
        #pragma unroll
        for (int kk = 0; kk < 4; kk++) {
            float4 w = sW4[(k4 * 4 + kk) * 8 + tc];
            unsigned long long wlo = pack2(w.x, w.y);
            unsigned long long whi = pack2(w.z, w.w);
            #pragma unroll
            for (int m = 0; m < 4; m++) {
                float xv = (kk == 0) ? xq[m].x : (kk == 1) ? xq[m].y
                          : (kk == 2) ? xq[m].z : xq[m].w;
                unsigned long long xp = pack2(xv, xv);
                ffma2(accp[m][0], xp, wlo);
                ffma2(accp[m][1], xp, whi);
            }
        }
    }

    float4 av_s = ((const float4*)att_src)[tc];
    float4 av_d = ((const float4*)att_dst)[tc];

    uint2* H2 = (uint2*)g_h2;
    #pragma unroll
    for (int m = 0; m < 4; m++) {
        float4 h;
        unpack2(accp[m][0], h.x, h.y);
        unpack2(accp[m][1], h.z, h.w);
        int gr = row0 + tr + 32 * m;
        if (gr < NN) {
            __half2 p01 = __floats2half2_rn(h.x, h.y);
            __half2 p23 = __floats2half2_rn(h.z, h.w);
            uint2 v;
            v.x = *(unsigned*)&p01;
            v.y = *(unsigned*)&p23;
            H2[(size_t)gr * 8 + tc] = v;
        }

        float s = h.x * av_s.x + h.y * av_s.y + h.z * av_s.z + h.w * av_s.w;
        float d = h.x * av_d.x + h.y * av_d.y + h.z * av_d.z + h.w * av_d.w;
        #pragma unroll
        for (int off = 4; off; off >>= 1) {
            s += __shfl_xor_sync(0xffffffffu, s, off);
            d += __shfl_xor_sync(0xffffffffu, d, off);
        }
        if (tc == 0 && gr < NN) {
            g_asrc2[gr] = s;
            g_adst2[gr] = d;
        }
    }
}

// ---------------- alpha pass L2 ---------------------------------------------
__global__ void k_alpha2(void) {
    int warp = threadIdx.x >> 5, lane = threadIdx.x & 31;
    int n = blockIdx.x * 16 + warp;
    if (n >= NN) return;
    int base = g_rowstart[n];
    int K = g_rowstart[n + 1] - base;
    float ad = g_adst2[n];

    float den = 0.f;
    for (int i = lane; i < K; i += 32) {
        int s = g_csr[base + i];
        float e = __expf(lrelu(g_asrc2[s] + ad));
        g_alpha2[base + i] = e;
        den += e;
    }
    #pragma unroll
    for (int off = 16; off; off >>= 1)
        den += __shfl_xor_sync(0xffffffffu, den, off);
    if (lane == 0)
        g_rden2[n] = 1.f / (den + 1e-16f);
}

// ---------------- aggregation L2: pure weighted gather ----------------------
__global__ void k_agg2(const float* __restrict__ b2, float* __restrict__ out) {
    int warp = threadIdx.x >> 5, lane = threadIdx.x & 31;
    int n = blockIdx.x * 16 + warp;
    if (n >= NN) return;
    int base = g_rowstart[n];
    int K = g_rowstart[n + 1] - base;
    const int* csr = g_csr + base;
    const float* AL = g_alpha2 + base;

    float acc = 0.f;
    int i = 0;
    for (; i + 3 < K; i += 4) {
        int s0 = csr[i], s1 = csr[i + 1], s2 = csr[i + 2], s3 = csr[i + 3];
        float e0 = AL[i], e1 = AL[i + 1], e2 = AL[i + 2], e3 = AL[i + 3];
        float h0 = __half2float(g_h2[(size_t)s0 * 32 + lane]);
        float h1 = __half2float(g_h2[(size_t)s1 * 32 + lane]);
        float h2 = __half2float(g_h2[(size_t)s2 * 32 + lane]);
        float h3 = __half2float(g_h2[(size_t)s3 * 32 + lane]);
        acc += (e0 * h0 + e1 * h1) + (e2 * h2 + e3 * h3);
    }
    for (; i < K; i++) {
        int s0 = csr[i];
        acc += AL[i] * __half2float(g_h2[(size_t)s0 * 32 + lane]);
    }
    out[(size_t)n * 32 + lane] = acc * g_rden2[n] + b2[lane];
}

// ---------------- launch ---------------------------------------------------
extern "C" void kernel_launch(void* const* d_in, const int* in_sizes, int n_in,
                              void* d_out, int out_size) {
    const float* x        = (const float*)d_in[0];
    const void*  ei       = d_in[1];
    const float* W1       = (const float*)d_in[2];
    const float* att_src1 = (const float*)d_in[3];
    const float* att_dst1 = (const float*)d_in[4];
    const float* b1       = (const float*)d_in[5];
    const float* W2       = (const float*)d_in[6];
    const float* att_src2 = (const float*)d_in[7];
    const float* att_dst2 = (const float*)d_in[8];
    const float* b2       = (const float*)d_in[9];
    float*       out      = (float*)d_out;

    const int SMEM_G2 = (128 * 32 + 128 * SX2_STRIDE) * 4;
    cudaFuncSetAttribute(k_gemm1, cudaFuncAttributeMaxDynamicSharedMemorySize, G1_SMEM);
    cudaFuncSetAttribute(k_gemm2, cudaFuncAttributeMaxDynamicSharedMemorySize, SMEM_G2);

    cudaStream_t s1;
    cudaStreamCreateWithFlags(&s1, cudaStreamNonBlocking);
    cudaEvent_t evA, evB;
    cudaEventCreateWithFlags(&evA, cudaEventDisableTiming);
    cudaEventCreateWithFlags(&evB, cudaEventDisableTiming);

    k_init<<<(NN + 255) / 256, 256>>>(ei, W1);                              // #1
    cudaEventRecord(evA, 0);
    cudaStreamWaitEvent(s1, evA, 0);

    k_count<<<(EE + 255) / 256, 256, 0, s1>>>(ei);                          // #2
    k_scan<<<NB_SCAN, 1024, 0, s1>>>();                                     // #3

    // main stream: HMMA GEMM1 (overlaps CSR build)
    k_gemm1<<<(NN + 63) / 64, 256, G1_SMEM>>>(x, att_src1, att_dst1);       // #4

    k_fill<<<(TE + 255) / 256, 256, 0, s1>>>(ei);                           // #5
    cudaEventRecord(evB, s1);

    cudaStreamWaitEvent(0, evB, 0);
    k_alpha1<<<(NN + 15) / 16, 512>>>();                                    // #6
    k_agg1<<<(NN + 15) / 16, 512>>>(b1);                                    // #7

    k_gemm2<<<(NN + 127) / 128, 256, SMEM_G2>>>(W2, att_src2, att_dst2);    // #8
    k_alpha2<<<(NN + 15) / 16, 512>>>();                                    // #9
    k_agg2<<<(NN + 15) / 16, 512>>>(b2, out);                               // #10
}

// round 16
// speedup vs baseline: 1.5580x; 1.5580x over previous
#include <cuda_runtime.h>
#include <cuda_fp16.h>
#include <cuda_bf16.h>
#include <cstdint>

#define NN 100000
#define EE 1600000
#define TE (EE + NN)
#define NB_SCAN ((NN + 1023) / 1024)
#define SX2_STRIDE 136

// ---------------- scratch (static device globals; no allocation) -----------
__device__ __align__(16) __half g_h1[NN * 128];    // layer1 linear output (fp16)
__device__ __align__(16) float  g_out1[NN * 128];  // relu(layer1 agg out)
__device__ __align__(16) __half g_h2[NN * 32];     // layer2 linear output (fp16)
__device__ __align__(16) float g_asrc1[NN * 4];
__device__ __align__(16) float g_adst1[NN * 4];
__device__ __align__(16) float g_asrc2[NN];
__device__ __align__(16) float g_adst2[NN];
__device__ __align__(16) unsigned short g_w1hi[128 * 136];  // bf16, padded [n][k]
__device__ __align__(16) unsigned short g_w1lo[128 * 136];
__device__ int   g_deg[NN];
__device__ int   g_rowstart[NN + 1];
__device__ int   g_cursor[NN];
__device__ int   g_csr[TE];
__device__ int   g_blockval[NB_SCAN];
__device__ int   g_blockflag[NB_SCAN];
__device__ int   g_is32;

// cheap leaky-relu: max(x, 0.2x) == lrelu(x) since 0.2 < 1
__device__ __forceinline__ float lrelu(float x) { return fmaxf(x, 0.2f * x); }

// packed f32x2 helpers (for gemm2)
__device__ __forceinline__ unsigned long long pack2(float a, float b) {
    unsigned long long r;
    asm("mov.b64 %0, {%1, %2};" : "=l"(r) : "f"(a), "f"(b));
    return r;
}
__device__ __forceinline__ void unpack2(unsigned long long p, float& a, float& b) {
    asm("mov.b64 {%0, %1}, %2;" : "=f"(a), "=f"(b) : "l"(p));
}
__device__ __forceinline__ void ffma2(unsigned long long& acc, unsigned long long a,
                                      unsigned long long b) {
    asm("fma.rn.f32x2 %0, %1, %2, %0;" : "+l"(acc) : "l"(a), "l"(b));
}

__device__ __forceinline__ uint32_t smem_u32(const void* p) {
    uint32_t a;
    asm("{ .reg .u64 t; cvta.to.shared.u64 t, %1; cvt.u32.u64 %0, t; }" : "=r"(a) : "l"(p));
    return a;
}

__device__ __forceinline__ void ldm4(uint32_t addr, uint32_t& r0, uint32_t& r1,
                                     uint32_t& r2, uint32_t& r3) {
    asm volatile("ldmatrix.sync.aligned.m8n8.x4.shared.b16 {%0,%1,%2,%3}, [%4];"
                 : "=r"(r0), "=r"(r1), "=r"(r2), "=r"(r3) : "r"(addr));
}

__device__ __forceinline__ void mma16816(float* c, uint32_t a0, uint32_t a1, uint32_t a2,
                                         uint32_t a3, uint32_t b0, uint32_t b1) {
    asm volatile(
        "mma.sync.aligned.m16n8k16.row.col.f32.bf16.bf16.f32 "
        "{%0,%1,%2,%3}, {%4,%5,%6,%7}, {%8,%9}, {%0,%1,%2,%3};"
        : "+f"(c[0]), "+f"(c[1]), "+f"(c[2]), "+f"(c[3])
        : "r"(a0), "r"(a1), "r"(a2), "r"(a3), "r"(b0), "r"(b1));
}

// ---------------- init + dtype detect + W1 bf16-split precompute -----------
__global__ void k_init(const void* __restrict__ ei, const float* __restrict__ W1) {
    int i = blockIdx.x * blockDim.x + threadIdx.x;
    if (i < NN) { g_deg[i] = 1; g_cursor[i] = 0; }
    if (i < NB_SCAN) g_blockflag[i] = 0;
    if (i < 16384) {
        int k = i >> 7, n = i & 127;
        float w = W1[i];
        __nv_bfloat16 hi = __float2bfloat16(w);
        __nv_bfloat16 lo = __float2bfloat16(w - __bfloat162float(hi));
        g_w1hi[n * 136 + k] = *(unsigned short*)&hi;
        g_w1lo[n * 136 + k] = *(unsigned short*)&lo;
    }
    if (i == 0) {
        const long long* p = (const long long*)ei;
        int bad = 0;
        for (int j = 0; j < 64; j++) {
            long long v = p[j];
            if (v < 0 || v >= NN) bad = 1;
        }
        g_is32 = bad;
    }
}

__device__ __forceinline__ int load_src(const void* ei, int e) {
    return g_is32 ? ((const int*)ei)[e] : (int)((const long long*)ei)[e];
}
__device__ __forceinline__ int load_dst(const void* ei, int e) {
    return g_is32 ? ((const int*)ei)[EE + e] : (int)((const long long*)ei)[EE + e];
}

// ---------------- CSR build -------------------------------------------------
__global__ void k_count(const void* __restrict__ ei) {
    int e = blockIdx.x * blockDim.x + threadIdx.x;
    if (e < EE) {
        int d = load_dst(ei, e);
        if ((unsigned)d < NN) atomicAdd(&g_deg[d], 1);
    }
}

__global__ void k_scan(void) {
    __shared__ int sh[1024];
    __shared__ int s_excl;
    int t = threadIdx.x;
    int b = blockIdx.x;
    int i = b * 1024 + t;
    int v = (i < NN) ? g_deg[i] : 0;
    sh[t] = v;
    __syncthreads();
    #pragma unroll
    for (int off = 1; off < 1024; off <<= 1) {
        int a = (t >= off) ? sh[t - off] : 0;
        __syncthreads();
        sh[t] += a;
        __syncthreads();
    }
    if (t == 1023) {
        g_blockval[b] = sh[1023];
        __threadfence();
        atomicExch(&g_blockflag[b], 1);
    }
    if (t < 32) {
        int excl = 0;
        for (int w0 = b - 1; w0 >= 0; w0 -= 32) {
            int idx = w0 - t;
            int val = 0;
            if (idx >= 0) {
                while (atomicAdd(&g_blockflag[idx], 0) == 0) {}
                __threadfence();
                val = g_blockval[idx];
            }
            #pragma unroll
            for (int off = 16; off; off >>= 1)
                val += __shfl_xor_sync(0xffffffffu, val, off);
            excl += val;
        }
        if (t == 0) s_excl = excl;
    }
    __syncthreads();
    if (i < NN) g_rowstart[i + 1] = sh[t] + s_excl;
    if (i == 0) g_rowstart[0] = 0;
}

__global__ void k_fill(const void* __restrict__ ei) {
    int t = blockIdx.x * blockDim.x + threadIdx.x;
    if (t >= TE) return;
    int s, d;
    if (t < EE) {
        s = load_src(ei, t);
        d = load_dst(ei, t);
    } else {
        s = d = t - EE;
    }
    if ((unsigned)s >= NN || (unsigned)d >= NN) return;
    int pos = g_rowstart[d] + atomicAdd(&g_cursor[d], 1);
    if ((unsigned)pos < TE) g_csr[pos] = s;
}

// ---------------- GEMM1 via mma.sync bf16 (split x3) + fused att1 ----------
#define XHI_OFF 1024
#define XLO_OFF 18432
#define WHI_OFF 35840
#define WLO_OFF 70656
#define G1_SMEM 105472

__global__ void __launch_bounds__(256, 2)
k_gemm1(const float* __restrict__ x,
        const float* __restrict__ att_src, const float* __restrict__ att_dst) {
    extern __shared__ char sm[];
    uint32_t smb = smem_u32(sm);
    int tid = threadIdx.x;
    int wid = tid >> 5, lane = tid & 31;
    int row0 = blockIdx.x * 64;

    float* s_as = (float*)(sm);
    float* s_ad = (float*)(sm + 512);
    if (tid < 128) {
        s_as[tid] = att_src[tid];
        s_ad[tid] = att_dst[tid];
    }

    {
        const uint4* WH4 = (const uint4*)g_w1hi;
        const uint4* WL4 = (const uint4*)g_w1lo;
        uint4* sWH = (uint4*)(sm + WHI_OFF);
        uint4* sWL = (uint4*)(sm + WLO_OFF);
        #pragma unroll
        for (int j = tid; j < 2176; j += 256) {
            sWH[j] = WH4[j];
            sWL[j] = WL4[j];
        }
    }

    {
        int r = tid >> 2;
        int ks = (tid & 3) * 32;
        int gr = row0 + r;
        const float4* X4 = (const float4*)x;
        char* xh = sm + XHI_OFF + r * 272 + ks * 2;
        char* xl = sm + XLO_OFF + r * 272 + ks * 2;
        #pragma unroll
        for (int j = 0; j < 8; j++) {
            float4 v = (gr < NN) ? X4[(size_t)gr * 32 + (ks >> 2) + j]
                                 : make_float4(0.f, 0.f, 0.f, 0.f);
            __nv_bfloat16 hx = __float2bfloat16(v.x);
            __nv_bfloat16 hy = __float2bfloat16(v.y);
            __nv_bfloat16 hz = __float2bfloat16(v.z);
            __nv_bfloat16 hw = __float2bfloat16(v.w);
            __nv_bfloat16 lx = __float2bfloat16(v.x - __bfloat162float(hx));
            __nv_bfloat16 ly = __float2bfloat16(v.y - __bfloat162float(hy));
            __nv_bfloat16 lz = __float2bfloat16(v.z - __bfloat162float(hz));
            __nv_bfloat16 lw = __float2bfloat16(v.w - __bfloat162float(hw));
            __nv_bfloat162 h01 = __halves2bfloat162(hx, hy);
            __nv_bfloat162 h23 = __halves2bfloat162(hz, hw);
            __nv_bfloat162 l01 = __halves2bfloat162(lx, ly);
            __nv_bfloat162 l23 = __halves2bfloat162(lz, lw);
            uint2 hv, lv;
            hv.x = *(uint32_t*)&h01; hv.y = *(uint32_t*)&h23;
            lv.x = *(uint32_t*)&l01; lv.y = *(uint32_t*)&l23;
            *(uint2*)(xh + j * 8) = hv;
            *(uint2*)(xl + j * 8) = lv;
        }
    }
    __syncthreads();

    int m0 = (wid >> 1) * 16;
    int ch = (wid & 1) * 64;
    int q = lane >> 3, rr = lane & 7;
    uint32_t aRow = (uint32_t)(m0 + rr + (q & 1) * 8);
    uint32_t aOffH = XHI_OFF + aRow * 272 + (uint32_t)(q >> 1) * 16;
    uint32_t aOffL = XLO_OFF + aRow * 272 + (uint32_t)(q >> 1) * 16;
    uint32_t bRow = (uint32_t)(ch + rr + (q >> 1) * 8);
    uint32_t bOffH = WHI_OFF + bRow * 272 + (uint32_t)(q & 1) * 16;
    uint32_t bOffL = WLO_OFF + bRow * 272 + (uint32_t)(q & 1) * 16;

    float c[8][4];
    #pragma unroll
    for (int nt = 0; nt < 8; nt++)
        #pragma unroll
        for (int e = 0; e < 4; e++) c[nt][e] = 0.f;

    #pragma unroll
    for (int kt = 0; kt < 8; kt++) {
        uint32_t ah0, ah1, ah2, ah3, al0, al1, al2, al3;
        ldm4(smb + aOffH + kt * 32, ah0, ah1, ah2, ah3);
        ldm4(smb + aOffL + kt * 32, al0, al1, al2, al3);
        #pragma unroll
        for (int np = 0; np < 4; np++) {
            uint32_t bh0, bh1, bh2, bh3, bl0, bl1, bl2, bl3;
            ldm4(smb + bOffH + np * 4352 + kt * 32, bh0, bh1, bh2, bh3);
            ldm4(smb + bOffL + np * 4352 + kt * 32, bl0, bl1, bl2, bl3);
            mma16816(c[np * 2],     ah0, ah1, ah2, ah3, bh0, bh1);
            mma16816(c[np * 2],     al0, al1, al2, al3, bh0, bh1);
            mma16816(c[np * 2],     ah0, ah1, ah2, ah3, bl0, bl1);
            mma16816(c[np * 2 + 1], ah0, ah1, ah2, ah3, bh2, bh3);
            mma16816(c[np * 2 + 1], al0, al1, al2, al3, bh2, bh3);
            mma16816(c[np * 2 + 1], ah0, ah1, ah2, ah3, bl2, bl3);
        }
    }

    int g = lane >> 2, qq = lane & 3;
    int gr0 = row0 + m0 + g;
    int gr1 = gr0 + 8;

    #pragma unroll
    for (int nt = 0; nt < 8; nt++) {
        int col = ch + nt * 8 + qq * 2;
        if (gr0 < NN)
            *(__half2*)&g_h1[(size_t)gr0 * 128 + col] = __floats2half2_rn(c[nt][0], c[nt][1]);
        if (gr1 < NN)
            *(__half2*)&g_h1[(size_t)gr1 * 128 + col] = __floats2half2_rn(c[nt][2], c[nt][3]);
    }

    #pragma unroll
    for (int hl = 0; hl < 2; hl++) {
        int gh = (ch >> 5) + hl;
        float s0 = 0.f, d0 = 0.f, s1 = 0.f, d1 = 0.f;
        #pragma unroll
        for (int t = 0; t < 4; t++) {
            int nt = hl * 4 + t;
            int col = ch + nt * 8 + qq * 2;
            float av0 = s_as[col], av1 = s_as[col + 1];
            float dv0 = s_ad[col], dv1 = s_ad[col + 1];
            s0 += c[nt][0] * av0 + c[nt][1] * av1;
            d0 += c[nt][0] * dv0 + c[nt][1] * dv1;
            s1 += c[nt][2] * av0 + c[nt][3] * av1;
            d1 += c[nt][2] * dv0 + c[nt][3] * dv1;
        }
        s0 += __shfl_xor_sync(0xffffffffu, s0, 1); s0 += __shfl_xor_sync(0xffffffffu, s0, 2);
        d0 += __shfl_xor_sync(0xffffffffu, d0, 1); d0 += __shfl_xor_sync(0xffffffffu, d0, 2);
        s1 += __shfl_xor_sync(0xffffffffu, s1, 1); s1 += __shfl_xor_sync(0xffffffffu, s1, 2);
        d1 += __shfl_xor_sync(0xffffffffu, d1, 1); d1 += __shfl_xor_sync(0xffffffffu, d1, 2);
        if (qq == 0) {
            if (gr0 < NN) { g_asrc1[gr0 * 4 + gh] = s0; g_adst1[gr0 * 4 + gh] = d0; }
            if (gr1 < NN) { g_asrc1[gr1 * 4 + gh] = s1; g_adst1[gr1 * 4 + gh] = d1; }
        }
    }
}

// ---------------- aggregation, layer 1 (R11 form: one node/warp) -----------
__global__ void k_agg1(const float* __restrict__ b1) {
    int warp = threadIdx.x >> 5, lane = threadIdx.x & 31;
    int n = blockIdx.x * 16 + warp;
    if (n >= NN) return;
    int base = g_rowstart[n];
    int K = g_rowstart[n + 1] - base;

    int head = lane >> 3;
    float ad_s = g_adst1[n * 4 + head];

    float den = 0.f;
    float4 acc = make_float4(0.f, 0.f, 0.f, 0.f);
    const uint2* H2 = (const uint2*)g_h1;
    const float* AS = g_asrc1;
    const int* csr = g_csr + base;

    int i = 0;
    for (; i + 3 < K; i += 4) {
        int s0 = csr[i], s1 = csr[i + 1], s2 = csr[i + 2], s3 = csr[i + 3];
        float a0 = AS[s0 * 4 + head];
        float a1 = AS[s1 * 4 + head];
        float a2 = AS[s2 * 4 + head];
        float a3 = AS[s3 * 4 + head];
        uint2 v0 = H2[(size_t)s0 * 32 + lane];
        uint2 v1 = H2[(size_t)s1 * 32 + lane];
        uint2 v2 = H2[(size_t)s2 * 32 + lane];
        uint2 v3 = H2[(size_t)s3 * 32 + lane];
        float e0 = __expf(lrelu(a0 + ad_s));
        float e1 = __expf(lrelu(a1 + ad_s));
        float e2 = __expf(lrelu(a2 + ad_s));
        float e3 = __expf(lrelu(a3 + ad_s));
        den += (e0 + e1) + (e2 + e3);
        float2 f0a = __half22float2(*(__half2*)&v0.x);
        float2 f0b = __half22float2(*(__half2*)&v0.y);
        float2 f1a = __half22float2(*(__half2*)&v1.x);
        float2 f1b = __half22float2(*(__half2*)&v1.y);
        float2 f2a = __half22float2(*(__half2*)&v2.x);
        float2 f2b = __half22float2(*(__half2*)&v2.y);
        float2 f3a = __half22float2(*(__half2*)&v3.x);
        float2 f3b = __half22float2(*(__half2*)&v3.y);
        acc.x += (e0 * f0a.x + e1 * f1a.x) + (e2 * f2a.x + e3 * f3a.x);
        acc.y += (e0 * f0a.y + e1 * f1a.y) + (e2 * f2a.y + e3 * f3a.y);
        acc.z += (e0 * f0b.x + e1 * f1b.x) + (e2 * f2b.x + e3 * f3b.x);
        acc.w += (e0 * f0b.y + e1 * f1b.y) + (e2 * f2b.y + e3 * f3b.y);
    }
    for (; i < K; i++) {
        int s0 = csr[i];
        float a0 = AS[s0 * 4 + head];
        uint2 v0 = H2[(size_t)s0 * 32 + lane];
        float e0 = __expf(lrelu(a0 + ad_s));
        den += e0;
        float2 f0a = __half22float2(*(__half2*)&v0.x);
        float2 f0b = __half22float2(*(__half2*)&v0.y);
        acc.x += e0 * f0a.x;
        acc.y += e0 * f0a.y;
        acc.z += e0 * f0b.x;
        acc.w += e0 * f0b.y;
    }

    float inv = 1.f / (den + 1e-16f);
    float4 b = ((const float4*)b1)[lane];
    float4 o;
    o.x = fmaxf(acc.x * inv + b.x, 0.f);
    o.y = fmaxf(acc.y * inv + b.y, 0.f);
    o.z = fmaxf(acc.z * inv + b.z, 0.f);
    o.w = fmaxf(acc.w * inv + b.w, 0.f);
    ((float4*)g_out1)[(size_t)n * 32 + lane] = o;
}

// ---------------- GEMM2: h2 = out1 @ W2 (128x32) + fused attention coeffs --
__global__ void k_gemm2(const float* __restrict__ W2,
                        const float* __restrict__ att_src, const float* __restrict__ att_dst) {
    extern __shared__ float smf[];
    float* sW = smf;
    float* sX = smf + 128 * 32;
    int tid = threadIdx.x;
    int row0 = blockIdx.x * 128;

    float4* sW4 = (float4*)sW;
    const float4* W4 = (const float4*)W2;
    for (int j = tid; j < 1024; j += 256) sW4[j] = W4[j];

    const float4* X4 = (const float4*)g_out1;
    for (int j = tid; j < 4096; j += 256) {
        int r = j >> 5, c = j & 31;
        int gr = row0 + r;
        float4 v = (gr < NN) ? X4[(size_t)gr * 32 + c] : make_float4(0.f, 0.f, 0.f, 0.f);
        *(float4*)&sX[r * SX2_STRIDE + c * 4] = v;
    }
    __syncthreads();

    int tc = tid & 7;
    int tr = tid >> 3;
    unsigned long long accp[4][2];
    #pragma unroll
    for (int m = 0; m < 4; m++) { accp[m][0] = 0ull; accp[m][1] = 0ull; }

    for (int k4 = 0; k4 < 32; k4++) {
        float4 xq[4];
        #pragma unroll
        for (int m = 0; m < 4; m++)
            xq[m] = *(const float4*)&sX[(tr + 32 * m) * SX2_STRIDE + k4 * 4];
        #pragma unroll
        for (int kk = 0; kk < 4; kk++) {
            float4 w = sW4[(k4 * 4 + kk) * 8 + tc];
            unsigned long long wlo = pack2(w.x, w.y);
            unsigned long long whi = pack2(w.z, w.w);
            #pragma unroll
            for (int m = 0; m < 4; m++) {
                float xv = (kk == 0) ? xq[m].x : (kk == 1) ? xq[m].y
                          : (kk == 2) ? xq[m].z : xq[m].w;
                unsigned long long xp = pack2(xv, xv);
                ffma2(accp[m][0], xp, wlo);
                ffma2(accp[m][1], xp, whi);
            }
        }
    }

    float4 av_s = ((const float4*)att_src)[tc];
    float4 av_d = ((const float4*)att_dst)[tc];

    uint2* H2 = (uint2*)g_h2;
    #pragma unroll
    for (int m = 0; m < 4; m++) {
        float4 h;
        unpack2(accp[m][0], h.x, h.y);
        unpack2(accp[m][1], h.z, h.w);
        int gr = row0 + tr + 32 * m;
        if (gr < NN) {
            __half2 p01 = __floats2half2_rn(h.x, h.y);
            __half2 p23 = __floats2half2_rn(h.z, h.w);
            uint2 v;
            v.x = *(unsigned*)&p01;
            v.y = *(unsigned*)&p23;
            H2[(size_t)gr * 8 + tc] = v;
        }

        float s = h.x * av_s.x + h.y * av_s.y + h.z * av_s.z + h.w * av_s.w;
        float d = h.x * av_d.x + h.y * av_d.y + h.z * av_d.z + h.w * av_d.w;
        #pragma unroll
        for (int off = 4; off; off >>= 1) {
            s += __shfl_xor_sync(0xffffffffu, s, off);
            d += __shfl_xor_sync(0xffffffffu, d, off);
        }
        if (tc == 0 && gr < NN) {
            g_asrc2[gr] = s;
            g_adst2[gr] = d;
        }
    }
}

// ---------------- aggregation, layer 2 (R11 form) --------------------------
__global__ void k_agg2(const float* __restrict__ b2, float* __restrict__ out) {
    int warp = threadIdx.x >> 5, lane = threadIdx.x & 31;
    int n = blockIdx.x * 16 + warp;
    if (n >= NN) return;
    int base = g_rowstart[n];
    int K = g_rowstart[n + 1] - base;
    float ad = g_adst2[n];
    const int* csr = g_csr + base;

    float den = 0.f, acc = 0.f;
    int i = 0;
    for (; i + 3 < K; i += 4) {
        int s0 = csr[i], s1 = csr[i + 1], s2 = csr[i + 2], s3 = csr[i + 3];
        float a0 = g_asrc2[s0];
        float a1 = g_asrc2[s1];
        float a2 = g_asrc2[s2];
        float a3 = g_asrc2[s3];
        float h0 = __half2float(g_h2[(size_t)s0 * 32 + lane]);
        float h1 = __half2float(g_h2[(size_t)s1 * 32 + lane]);
        float h2 = __half2float(g_h2[(size_t)s2 * 32 + lane]);
        float h3 = __half2float(g_h2[(size_t)s3 * 32 + lane]);
        float e0 = __expf(lrelu(a0 + ad));
        float e1 = __expf(lrelu(a1 + ad));
        float e2 = __expf(lrelu(a2 + ad));
        float e3 = __expf(lrelu(a3 + ad));
        den += (e0 + e1) + (e2 + e3);
        acc += (e0 * h0 + e1 * h1) + (e2 * h2 + e3 * h3);
    }
    for (; i < K; i++) {
        int s0 = csr[i];
        float e0 = __expf(lrelu(g_asrc2[s0] + ad));
        den += e0;
        acc += e0 * __half2float(g_h2[(size_t)s0 * 32 + lane]);
    }
    out[(size_t)n * 32 + lane] = acc / (den + 1e-16f) + b2[lane];
}

// ---------------- launch ---------------------------------------------------
extern "C" void kernel_launch(void* const* d_in, const int* in_sizes, int n_in,
                              void* d_out, int out_size) {
    const float* x        = (const float*)d_in[0];
    const void*  ei       = d_in[1];
    const float* W1       = (const float*)d_in[2];
    const float* att_src1 = (const float*)d_in[3];
    const float* att_dst1 = (const float*)d_in[4];
    const float* b1       = (const float*)d_in[5];
    const float* W2       = (const float*)d_in[6];
    const float* att_src2 = (const float*)d_in[7];
    const float* att_dst2 = (const float*)d_in[8];
    const float* b2       = (const float*)d_in[9];
    float*       out      = (float*)d_out;

    const int SMEM_G2 = (128 * 32 + 128 * SX2_STRIDE) * 4;
    cudaFuncSetAttribute(k_gemm1, cudaFuncAttributeMaxDynamicSharedMemorySize, G1_SMEM);
    cudaFuncSetAttribute(k_gemm2, cudaFuncAttributeMaxDynamicSharedMemorySize, SMEM_G2);

    cudaStream_t s1;
    cudaStreamCreateWithFlags(&s1, cudaStreamNonBlocking);
    cudaEvent_t evA, evB;
    cudaEventCreateWithFlags(&evA, cudaEventDisableTiming);
    cudaEventCreateWithFlags(&evB, cudaEventDisableTiming);

    k_init<<<(NN + 255) / 256, 256>>>(ei, W1);                              // #1
    cudaEventRecord(evA, 0);
    cudaStreamWaitEvent(s1, evA, 0);

    k_count<<<(EE + 255) / 256, 256, 0, s1>>>(ei);                          // #2
    k_scan<<<NB_SCAN, 1024, 0, s1>>>();                                     // #3

    // main stream: HMMA GEMM1 (overlaps CSR build)
    k_gemm1<<<(NN + 63) / 64, 256, G1_SMEM>>>(x, att_src1, att_dst1);       // #4

    k_fill<<<(TE + 255) / 256, 256, 0, s1>>>(ei);                           // #5
    cudaEventRecord(evB, s1);

    cudaStreamWaitEvent(0, evB, 0);
    k_agg1<<<(NN + 15) / 16, 512>>>(b1);                                    // #6

    k_gemm2<<<(NN + 127) / 128, 256, SMEM_G2>>>(W2, att_src2, att_dst2);    // #7
    k_agg2<<<(NN + 15) / 16, 512>>>(b2, out);                               // #8
}